// round 13
// baseline (speedup 1.0000x reference)
#include <cuda_runtime.h>
#include <cuda_fp16.h>
#include <mma.h>
#include <cstdint>

using namespace nvcuda;
typedef unsigned int u32;

#define MT 64
#define LDH 264            // hs fp16 stride (528B rows)
#define LDFS 260           // fs fp32 stride
#define LDLW 36            // lfwt fp32 stride
#define LDLO 32            // lfout fp32 stride
#define NCHUNK 16
#define CHUNK_BYTES (16 * LDH * 2)   // 8448

// ---------------- smem layout (floats) ----------------
#define HS_F    0
#define B_F     8448
#define GEO_F   16896
#define LFWT_F  17536
#define LFO_F   26752
#define LFB_F   28800
#define MBAR_F  28832               // 5 mbarriers x 8B = 40B (16B-aligned start)
#define SMEM_FLOATS 28844           // 115,376 B -> 2 CTAs/SM

__device__ __half g_w2hp[256 * LDH];   // [K][264] fp16, padded rows (bulk-copyable)
__device__ float  g_lfwt[256 * LDLW];  // [K=256][36] padded lfw

__device__ __forceinline__ u32 smem_u32(const void* p) {
    return (u32)__cvta_generic_to_shared(p);
}
__device__ __forceinline__ void cp_async16(u32 s, const void* g) {
    asm volatile("cp.async.cg.shared.global [%0], [%1], 16;" :: "r"(s), "l"(g));
}
__device__ __forceinline__ void cp_commit() { asm volatile("cp.async.commit_group;"); }
template<int NN> __device__ __forceinline__ void cp_wait() {
    asm volatile("cp.async.wait_group %0;" :: "n"(NN) : "memory");
}
__device__ __forceinline__ void mbar_init(u32 mbar, u32 cnt) {
    asm volatile("mbarrier.init.shared.b64 [%0], %1;" :: "r"(mbar), "r"(cnt) : "memory");
}
__device__ __forceinline__ void mbar_expect_tx(u32 mbar, u32 bytes) {
    asm volatile("mbarrier.arrive.expect_tx.shared.b64 _, [%0], %1;" :: "r"(mbar), "r"(bytes) : "memory");
}
__device__ __forceinline__ void bulk_g2s(u32 dst, const void* src, u32 bytes, u32 mbar) {
    asm volatile("cp.async.bulk.shared::cluster.global.mbarrier::complete_tx::bytes [%0], [%1], %2, [%3];"
                 :: "r"(dst), "l"(src), "r"(bytes), "r"(mbar) : "memory");
}
__device__ __forceinline__ void mbar_wait(u32 mbar, u32 parity) {
    u32 done;
    asm volatile("{\n\t.reg .pred p;\n\t"
                 "mbarrier.try_wait.parity.acquire.cta.shared::cta.b64 p, [%1], %2;\n\t"
                 "selp.b32 %0, 1, 0, p;\n\t}"
                 : "=r"(done) : "r"(mbar), "r"(parity) : "memory");
    if (!done) {
        asm volatile("{\n\t.reg .pred P1;\n\t"
                     "WAIT_LOOP_%=:\n\t"
                     "mbarrier.try_wait.parity.acquire.cta.shared::cta.b64 P1, [%0], %1, 0x989680;\n\t"
                     "@P1 bra.uni WAIT_DONE_%=;\n\t"
                     "bra.uni WAIT_LOOP_%=;\n\t"
                     "WAIT_DONE_%=:\n\t}"
                     :: "r"(mbar), "r"(parity) : "memory");
    }
}

__global__ void w2_convert_kernel(const float* __restrict__ w2,
                                  const float* __restrict__ lfw) {
    const int k = blockIdx.x, n = threadIdx.x;
    g_w2hp[k * LDH + n] = __float2half(w2[k * 256 + n]);
    if (n < 8) g_w2hp[k * LDH + 256 + n] = __float2half(0.f);
    if (n < LDLW)
        g_lfwt[k * LDLW + n] = (n < 18) ? lfw[k * 18 + n] : 0.f;
}

// =================== Fused kernel ===================
__global__ void __launch_bounds__(256, 2)
gauss_fused_kernel(const float* __restrict__ mu, const float* __restrict__ sc,
                   const float* __restrict__ rot, const float* __restrict__ Q,
                   const float* __restrict__ w1, const float* __restrict__ b1,
                   const float* __restrict__ gamma, const float* __restrict__ beta,
                   const float* __restrict__ b2, const float* __restrict__ lfb,
                   float* __restrict__ out, int N)
{
    extern __shared__ float sm[];
    const u32 smb = smem_u32(sm);
    __half* hs  = (__half*)(sm + HS_F);
    float* fs   = sm + HS_F;            // overlays hs+B post-GEMM
    float* mus  = sm + GEO_F;           // 192
    float* scs  = sm + GEO_F + 192;     // 192
    float* rots = sm + GEO_F + 384;     // 256
    float* lfwt = sm + LFWT_F;
    float* lfo  = sm + LFO_F;
    float* lfbs = sm + LFB_F;
    const u32 mb0 = smb + MBAR_F * 4;   // 4 B-chunk mbarriers at mb0 + 8*i
    const u32 mbG = mb0 + 32;           // lfwt mbarrier

    const int tid  = threadIdx.x;
    const int lane = tid & 31;
    const int wid  = tid >> 5;
    const int rowBase = blockIdx.x * MT;
    const bool fullTile = (rowBase + MT <= N);

    // ---- geo via cp.async (small) ----
    if (fullTile) {
        if (tid < 48)
            cp_async16(smb + (GEO_F + tid * 4) * 4, mu + (size_t)rowBase * 3 + tid * 4);
        else if (tid >= 64 && tid < 112)
            cp_async16(smb + (GEO_F + 192 + (tid - 64) * 4) * 4, sc + (size_t)rowBase * 3 + (tid - 64) * 4);
        else if (tid >= 128 && tid < 192)
            cp_async16(smb + (GEO_F + 384 + (tid - 128) * 4) * 4, rot + (size_t)rowBase * 4 + (tid - 128) * 4);
    } else {
        #pragma unroll 1
        for (int idx = tid; idx < 640; idx += 256) {
            float v = 0.f;
            if (idx < 192)      { const int r = idx / 3;         if (rowBase + r < N) v = mu[(size_t)(rowBase + r) * 3 + idx % 3]; }
            else if (idx < 384) { const int r = (idx - 192) / 3; if (rowBase + r < N) v = sc[(size_t)(rowBase + r) * 3 + (idx - 192) % 3]; }
            else                { const int r = (idx - 384) / 4; if (rowBase + r < N) v = rot[(size_t)(rowBase + r) * 4 + (idx - 384) % 4]; }
            sm[GEO_F + idx] = v;
        }
    }
    cp_commit();

    // ---- mbarrier init, then bulk copies (lfwt + first 3 B chunks) ----
    if (tid == 0) {
        #pragma unroll
        for (int i = 0; i < 5; ++i) mbar_init(mb0 + i * 8, 1);
    }
    if (tid < 18) lfbs[tid] = lfb[tid];
    const float4 b2v4 = __ldg((const float4*)(b2 + (tid & 63) * 4));
    __syncthreads();    // mbarrier init visible to async proxy use below
    if (tid == 0) {
        mbar_expect_tx(mbG, 256 * LDLW * 4);
        bulk_g2s(smb + LFWT_F * 4, g_lfwt, 256 * LDLW * 4, mbG);
        #pragma unroll
        for (int c = 0; c < 3; ++c) {
            mbar_expect_tx(mb0 + c * 8, CHUNK_BYTES);
            bulk_g2s(smb + B_F * 4 + c * CHUNK_BYTES, g_w2hp + c * 16 * LDH, CHUNK_BYTES, mb0 + c * 8);
        }
    }
    cp_wait<0>();        // geo done
    __syncthreads();

    // ---- phase 1: h = relu(LN(geo@w1+b1)) -> hs fp16 ; 4-row batches ----
    #pragma unroll 1
    for (int bb = 0; bb < 2; ++bb) {
        const int rl0 = wid * 8 + bb * 4;
        float g[4][10];
        #pragma unroll
        for (int r = 0; r < 4; ++r) {
            const int rl = rl0 + r;
            g[r][0]=mus[rl*3]; g[r][1]=mus[rl*3+1]; g[r][2]=mus[rl*3+2];
            g[r][3]=scs[rl*3]; g[r][4]=scs[rl*3+1]; g[r][5]=scs[rl*3+2];
            g[r][6]=rots[rl*4]; g[r][7]=rots[rl*4+1]; g[r][8]=rots[rl*4+2]; g[r][9]=rots[rl*4+3];
        }
        float hv[4][8];
        #pragma unroll
        for (int jj = 0; jj < 8; ++jj) {
            const int d = lane + 32 * jj;
            float w[10];
            #pragma unroll
            for (int i = 0; i < 10; ++i) w[i] = __ldg(w1 + i * 256 + d);
            const float bv = __ldg(b1 + d);
            #pragma unroll
            for (int r = 0; r < 4; ++r) {
                float a = bv;
                #pragma unroll
                for (int i = 0; i < 10; ++i) a = fmaf(g[r][i], w[i], a);
                hv[r][jj] = a;
            }
        }
        float s[4] = {0.f, 0.f, 0.f, 0.f};
        #pragma unroll
        for (int r = 0; r < 4; ++r)
            #pragma unroll
            for (int jj = 0; jj < 8; ++jj) s[r] += hv[r][jj];
        #pragma unroll
        for (int o = 16; o; o >>= 1) {
            #pragma unroll
            for (int r = 0; r < 4; ++r) s[r] += __shfl_xor_sync(0xffffffffu, s[r], o);
        }
        float v[4] = {0.f, 0.f, 0.f, 0.f};
        float mean[4];
        #pragma unroll
        for (int r = 0; r < 4; ++r) {
            mean[r] = s[r] * (1.f/256.f);
            #pragma unroll
            for (int jj = 0; jj < 8; ++jj) { float t = hv[r][jj] - mean[r]; v[r] = fmaf(t, t, v[r]); }
        }
        #pragma unroll
        for (int o = 16; o; o >>= 1) {
            #pragma unroll
            for (int r = 0; r < 4; ++r) v[r] += __shfl_xor_sync(0xffffffffu, v[r], o);
        }
        #pragma unroll
        for (int r = 0; r < 4; ++r) {
            const float inv = rsqrtf(v[r] * (1.f/256.f) + 1e-5f);
            const bool valid = (rowBase + rl0 + r < N);
            #pragma unroll
            for (int jj = 0; jj < 8; ++jj) {
                const int d = lane + 32 * jj;
                float t = (hv[r][jj] - mean[r]) * inv * __ldg(gamma + d) + __ldg(beta + d);
                t = fmaxf(t, 0.f);
                if (!valid) t = 0.f;
                hs[(rl0 + r) * LDH + d] = __float2half(t);
            }
        }
    }
    __syncthreads();

    // ---- phase 2: GEMM 64x256x256, warp tile 64x32, bulk-fed 4-buf pipeline ----
    const int c0 = wid * 32;

    wmma::fragment<wmma::accumulator, 16,16,16, float> acc[4][2];
    #pragma unroll
    for (int mi = 0; mi < 4; ++mi)
        #pragma unroll
        for (int ni = 0; ni < 2; ++ni) wmma::fill_fragment(acc[mi][ni], 0.f);

    #pragma unroll 1
    for (int t = 0; t < NCHUNK; ++t) {
        mbar_wait(mb0 + (t & 3) * 8, (t >> 2) & 1);

        const __half* bh0 = (const __half*)(sm + B_F) + (t & 3) * (16 * LDH);
        const int kk = t * 16;

        wmma::fragment<wmma::matrix_a, 16,16,16, __half, wmma::row_major> a[4];
        #pragma unroll
        for (int mi = 0; mi < 4; ++mi)
            wmma::load_matrix_sync(a[mi], hs + (mi*16) * LDH + kk, LDH);

        #pragma unroll
        for (int ni = 0; ni < 2; ++ni) {
            wmma::fragment<wmma::matrix_b, 16,16,16, __half, wmma::row_major> b;
            wmma::load_matrix_sync(b, bh0 + c0 + ni*16, LDH);
            #pragma unroll
            for (int mi = 0; mi < 4; ++mi)
                wmma::mma_sync(acc[mi][ni], a[mi], b, acc[mi][ni]);
        }
        __syncthreads();   // all warps done with buf (t&3)
        if (t + 3 < NCHUNK && tid == 0) {
            const int c = t + 3;
            mbar_expect_tx(mb0 + (c & 3) * 8, CHUNK_BYTES);
            bulk_g2s(smb + B_F * 4 + (c & 3) * CHUNK_BYTES, g_w2hp + c * 16 * LDH,
                     CHUNK_BYTES, mb0 + (c & 3) * 8);
        }
    }
    __syncthreads();   // hs + B dead; fs takes over

    // ---- phase 3: acc -> fs ; features = fs + b2 + Q -> out + fs (float4) ----
    #pragma unroll
    for (int mi = 0; mi < 4; ++mi)
        #pragma unroll
        for (int ni = 0; ni < 2; ++ni)
            wmma::store_matrix_sync(fs + (mi*16) * LDFS + c0 + ni*16,
                                    acc[mi][ni], LDFS, wmma::mem_row_major);
    __syncthreads();

    {
        const int rq = tid >> 6;             // 0..3
        const int c4 = (tid & 63) * 4;       // col group base
        #pragma unroll 1
        for (int g = 0; g < 4; ++g) {
            float4 qv[4];
            #pragma unroll
            for (int k = 0; k < 4; ++k) {
                const int rloc = g * 16 + k * 4 + rq;
                const int row = rowBase + rloc;
                qv[k] = (row < N) ? *(const float4*)&Q[(size_t)row * 256 + c4]
                                  : make_float4(0.f, 0.f, 0.f, 0.f);
            }
            #pragma unroll
            for (int k = 0; k < 4; ++k) {
                const int rloc = g * 16 + k * 4 + rq;
                const int row = rowBase + rloc;
                float4 fv = *(const float4*)&fs[rloc * LDFS + c4];
                fv.x = fv.x + b2v4.x + qv[k].x;
                fv.y = fv.y + b2v4.y + qv[k].y;
                fv.z = fv.z + b2v4.z + qv[k].z;
                fv.w = fv.w + b2v4.w + qv[k].w;
                if (row < N) *(float4*)&out[(size_t)row * 256 + c4] = fv;
                *(float4*)&fs[rloc * LDFS + c4] = fv;
            }
        }
    }
    mbar_wait(mbG, 0);    // lfwt staged (long done)
    __syncthreads();

    // ---- phase 3.5: lf logits = fs @ lfwt via tf32 wmma (64x32x256) ----
    {
        const int wm = wid & 3;       // 16-row frag
        const int nf = wid >> 2;      // 16-col frag (0/1)
        wmma::fragment<wmma::accumulator, 16,16,8, float> lacc;
        wmma::fill_fragment(lacc, 0.f);
        #pragma unroll 1
        for (int k = 0; k < 256; k += 8) {
            wmma::fragment<wmma::matrix_a, 16,16,8, wmma::precision::tf32, wmma::row_major> la;
            wmma::fragment<wmma::matrix_b, 16,16,8, wmma::precision::tf32, wmma::row_major> lb;
            wmma::load_matrix_sync(la, fs + (wm*16) * LDFS + k, LDFS);
            wmma::load_matrix_sync(lb, lfwt + k * LDLW + nf*16, LDLW);
            #pragma unroll
            for (int e = 0; e < la.num_elements; ++e) la.x[e] = wmma::__float_to_tf32(la.x[e]);
            #pragma unroll
            for (int e = 0; e < lb.num_elements; ++e) lb.x[e] = wmma::__float_to_tf32(lb.x[e]);
            wmma::mma_sync(lacc, la, lb, lacc);
        }
        wmma::store_matrix_sync(lfo + (wm*16) * LDLO + nf*16, lacc, LDLO, wmma::mem_row_major);
    }
    __syncthreads();

    // ---- phase 4: sigmoid + corners + refs ----
    {
        const int rl    = wid * 8 + (lane >> 2);
        const int cpart = lane & 3;
        const int row   = rowBase + rl;

        if (row < N) {
            const float mx = mus[rl*3], my = mus[rl*3+1], mz = mus[rl*3+2];
            const float sx = scs[rl*3]*0.5f, sy = scs[rl*3+1]*0.5f, sz = scs[rl*3+2]*0.5f;
            float qw = rots[rl*4], qx = rots[rl*4+1], qy = rots[rl*4+2], qz = rots[rl*4+3];
            const float nrm = fmaxf(sqrtf(qw*qw + qx*qx + qy*qy + qz*qz), 1e-8f);
            const float inr = 1.f / nrm;
            qw *= inr; qx *= inr; qy *= inr; qz *= inr;
            const float r00 = 1.f - 2.f*(qy*qy + qz*qz), r01 = 2.f*(qx*qy - qz*qw), r02 = 2.f*(qx*qz + qy*qw);
            const float r10 = 2.f*(qx*qy + qz*qw), r11 = 1.f - 2.f*(qx*qx + qz*qz), r12 = 2.f*(qy*qz - qx*qw);
            const float r20 = 2.f*(qx*qz - qy*qw), r21 = 2.f*(qy*qz + qx*qw), r22 = 1.f - 2.f*(qx*qx + qy*qy);

            const size_t OUT_CORN = (size_t)N * 256;
            const size_t OUT_XY   = OUT_CORN + (size_t)N * 33;
            const size_t OUT_XZ   = OUT_XY + (size_t)N * 22;
            const size_t OUT_YZ   = OUT_XZ + (size_t)N * 22;
            const float invxy = 1.f / (102.4f + 1e-6f);
            const float invz  = 1.f / (8.0f + 1e-6f);

            #pragma unroll
            for (int mm = 0; mm < 3; ++mm) {
                const int m = cpart + mm * 4;
                if (m < 11) {
                    float lx, ly, lz;
                    if (m == 0)      { lx = 0.f;  ly = 0.f;  lz = 0.f; }
                    else if (m == 1) { lx = 0.f;  ly = sy;   lz = 0.f; }
                    else if (m == 2) { lx = 0.f;  ly = -sy;  lz = 0.f; }
                    else if (m == 3) { lx = sx;   ly = 0.f;  lz = 0.f; }
                    else if (m == 4) { lx = -sx;  ly = 0.f;  lz = 0.f; }
                    else {
                        const int j = (m - 5) * 3;
                        const float t0 = lfo[rl * LDLO + j]     + lfbs[j];
                        const float t1 = lfo[rl * LDLO + j + 1] + lfbs[j + 1];
                        const float t2 = lfo[rl * LDLO + j + 2] + lfbs[j + 2];
                        const float g0 = 1.f / (1.f + __expf(-t0));
                        const float g1 = 1.f / (1.f + __expf(-t1));
                        const float g2 = 1.f / (1.f + __expf(-t2));
                        lx = (g0 - 0.5f) * sx;
                        ly = (g1 - 0.5f) * sy;
                        lz = (g2 - 0.5f) * sz;
                    }
                    const float cxv = r00*lx + r01*ly + r02*lz + mx;
                    const float cyv = r10*lx + r11*ly + r12*lz + my;
                    const float czv = r20*lx + r21*ly + r22*lz + mz;
                    const size_t cb = OUT_CORN + ((size_t)row * 11 + m) * 3;
                    out[cb]   = cxv;
                    out[cb+1] = cyv;
                    out[cb+2] = czv;
                    const float nx = fminf(fmaxf((cxv + 51.2f) * invxy, 0.f), 1.f);
                    const float ny = fminf(fmaxf((cyv + 51.2f) * invxy, 0.f), 1.f);
                    const float nz = fminf(fmaxf((czv + 5.0f)  * invz,  0.f), 1.f);
                    const size_t rb2 = (size_t)row * 11 + m;
                    *(float2*)&out[OUT_XY + rb2*2] = make_float2(nx, ny);
                    *(float2*)&out[OUT_XZ + rb2*2] = make_float2(nx, nz);
                    *(float2*)&out[OUT_YZ + rb2*2] = make_float2(ny, nz);
                }
            }
        }
    }
}

extern "C" void kernel_launch(void* const* d_in, const int* in_sizes, int n_in,
                              void* d_out, int out_size) {
    const float* mu    = (const float*)d_in[0];
    const float* sc    = (const float*)d_in[1];
    const float* rot   = (const float*)d_in[2];
    const float* Q     = (const float*)d_in[3];
    const float* w1    = (const float*)d_in[4];
    const float* b1    = (const float*)d_in[5];
    const float* gamma = (const float*)d_in[6];
    const float* beta  = (const float*)d_in[7];
    const float* w2    = (const float*)d_in[8];
    const float* b2    = (const float*)d_in[9];
    const float* lfw   = (const float*)d_in[10];
    const float* lfb   = (const float*)d_in[11];
    float* out = (float*)d_out;
    const int N = in_sizes[0] / 3;

    w2_convert_kernel<<<256, 256>>>(w2, lfw);

    const int smem = SMEM_FLOATS * sizeof(float);
    cudaFuncSetAttribute(gauss_fused_kernel,
                         cudaFuncAttributeMaxDynamicSharedMemorySize, smem);
    const int blocks = (N + MT - 1) / MT;
    gauss_fused_kernel<<<blocks, 256, smem>>>(
        mu, sc, rot, Q, w1, b1, gamma, beta, b2, lfb, out, N);
}

// round 14
// speedup vs baseline: 1.0306x; 1.0306x over previous
#include <cuda_runtime.h>
#include <cuda_fp16.h>
#include <mma.h>
#include <cstdint>

using namespace nvcuda;
typedef unsigned int u32;

#define MT 64
#define LDH 264            // hs fp16 stride (528B rows)
#define LDFS 260           // fs fp32 stride
#define LDLW 36            // lfwt fp32 stride
#define LDLO 32            // lfout fp32 stride
#define NCHUNK 16

// ---------------- smem layout (floats) ----------------
#define HS_F    0
#define B_F     8448
#define GEO_F   16896
#define LFWT_F  17536
#define LFO_F   26752
#define LFB_F   28800
#define SMEM_FLOATS 28832            // 115,328 B -> 2 CTAs/SM

__device__ __half g_w2h[256 * 256];    // [K][N] fp16
__device__ float  g_lfwt[256 * LDLW];  // [K=256][36] padded lfw, tf32-pre-rounded

__device__ __forceinline__ u32 smem_u32(const void* p) {
    return (u32)__cvta_generic_to_shared(p);
}
__device__ __forceinline__ void cp_async16(u32 s, const void* g) {
    asm volatile("cp.async.cg.shared.global [%0], [%1], 16;" :: "r"(s), "l"(g));
}
__device__ __forceinline__ void cp_commit() { asm volatile("cp.async.commit_group;"); }
template<int NN> __device__ __forceinline__ void cp_wait() {
    asm volatile("cp.async.wait_group %0;" :: "n"(NN) : "memory");
}
__device__ __forceinline__ float to_tf32(float x) {
    float r;
    asm("cvt.rna.tf32.f32 %0, %1;" : "=f"(r) : "f"(x));
    return r;
}

__global__ void w2_convert_kernel(const float* __restrict__ w2,
                                  const float* __restrict__ lfw) {
    const int k = blockIdx.x, n = threadIdx.x;
    g_w2h[k * 256 + n] = __float2half(w2[k * 256 + n]);
    if (n < LDLW)
        g_lfwt[k * LDLW + n] = (n < 18) ? to_tf32(lfw[k * 18 + n]) : 0.f;
}

// stage a 16-k-row chunk of w2 fp16 into buffer buf (0..3)
__device__ __forceinline__ void load_chunk(u32 smb, int buf, int kt, int tid) {
    const u32 base = smb + B_F * 4 + buf * 8448;
    #pragma unroll
    for (int q = 0; q < 2; ++q) {
        const int idx = tid + 256 * q;          // 0..511
        const int r   = idx >> 5;               // k-row 0..15
        const int j   = idx & 31;               // 8-fp16 chunk
        cp_async16(base + r * 528 + j * 16, g_w2h + (kt + r) * 256 + j * 8);
    }
}

// =================== Fused kernel ===================
__global__ void __launch_bounds__(256, 2)
gauss_fused_kernel(const float* __restrict__ mu, const float* __restrict__ sc,
                   const float* __restrict__ rot, const float* __restrict__ Q,
                   const float* __restrict__ w1, const float* __restrict__ b1,
                   const float* __restrict__ gamma, const float* __restrict__ beta,
                   const float* __restrict__ b2, const float* __restrict__ lfb,
                   float* __restrict__ out, int N)
{
    extern __shared__ float sm[];
    const u32 smb = smem_u32(sm);
    __half* hs  = (__half*)(sm + HS_F);
    float* fs   = sm + HS_F;            // overlays hs+B post-GEMM
    float* mus  = sm + GEO_F;           // 192
    float* scs  = sm + GEO_F + 192;     // 192
    float* rots = sm + GEO_F + 384;     // 256
    float* lfwt = sm + LFWT_F;
    float* lfo  = sm + LFO_F;
    float* lfbs = sm + LFB_F;

    const int tid  = threadIdx.x;
    const int lane = tid & 31;
    const int wid  = tid >> 5;
    const int rowBase = blockIdx.x * MT;
    const bool fullTile = (rowBase + MT <= N);

    // ---- group G: lfwt + geo ----
    {
        const u32 lfdst = smb + LFWT_F * 4;
        #pragma unroll
        for (int q = 0; q < 9; ++q) {
            const int c = tid + 256 * q;      // 0..2303 chunks of 16B
            cp_async16(lfdst + c * 16, g_lfwt + c * 4);
        }
        if (fullTile) {
            if (tid < 48)
                cp_async16(smb + (GEO_F + tid * 4) * 4, mu + (size_t)rowBase * 3 + tid * 4);
            else if (tid >= 64 && tid < 112)
                cp_async16(smb + (GEO_F + 192 + (tid - 64) * 4) * 4, sc + (size_t)rowBase * 3 + (tid - 64) * 4);
            else if (tid >= 128 && tid < 192)
                cp_async16(smb + (GEO_F + 384 + (tid - 128) * 4) * 4, rot + (size_t)rowBase * 4 + (tid - 128) * 4);
        } else {
            #pragma unroll 1
            for (int idx = tid; idx < 640; idx += 256) {
                float v = 0.f;
                if (idx < 192)      { const int r = idx / 3;         if (rowBase + r < N) v = mu[(size_t)(rowBase + r) * 3 + idx % 3]; }
                else if (idx < 384) { const int r = (idx - 192) / 3; if (rowBase + r < N) v = sc[(size_t)(rowBase + r) * 3 + (idx - 192) % 3]; }
                else                { const int r = (idx - 384) / 4; if (rowBase + r < N) v = rot[(size_t)(rowBase + r) * 4 + (idx - 384) % 4]; }
                sm[GEO_F + idx] = v;
            }
        }
    }
    cp_commit();                                     // [G]
    load_chunk(smb, 0, 0, tid);  cp_commit();        // [G][B0]
    load_chunk(smb, 1, 16, tid); cp_commit();        // [G][B0][B1]
    load_chunk(smb, 2, 32, tid); cp_commit();        // [G][B0][B1][B2]

    if (tid < 18) lfbs[tid] = lfb[tid];
    const float4 b2v4 = __ldg((const float4*)(b2 + (tid & 63) * 4));

    cp_wait<3>();          // G done; B0..B2 in flight
    __syncthreads();

    // ---- phase 1: h = relu(LN(geo@w1+b1)) -> hs fp16 ; 4-row batches ----
    #pragma unroll 1
    for (int bb = 0; bb < 2; ++bb) {
        const int rl0 = wid * 8 + bb * 4;
        float g[4][10];
        #pragma unroll
        for (int r = 0; r < 4; ++r) {
            const int rl = rl0 + r;
            g[r][0]=mus[rl*3]; g[r][1]=mus[rl*3+1]; g[r][2]=mus[rl*3+2];
            g[r][3]=scs[rl*3]; g[r][4]=scs[rl*3+1]; g[r][5]=scs[rl*3+2];
            g[r][6]=rots[rl*4]; g[r][7]=rots[rl*4+1]; g[r][8]=rots[rl*4+2]; g[r][9]=rots[rl*4+3];
        }
        float hv[4][8];
        #pragma unroll
        for (int jj = 0; jj < 8; ++jj) {
            const int d = lane + 32 * jj;
            float w[10];
            #pragma unroll
            for (int i = 0; i < 10; ++i) w[i] = __ldg(w1 + i * 256 + d);
            const float bv = __ldg(b1 + d);
            #pragma unroll
            for (int r = 0; r < 4; ++r) {
                float a = bv;
                #pragma unroll
                for (int i = 0; i < 10; ++i) a = fmaf(g[r][i], w[i], a);
                hv[r][jj] = a;
            }
        }
        float s[4] = {0.f, 0.f, 0.f, 0.f};
        #pragma unroll
        for (int r = 0; r < 4; ++r)
            #pragma unroll
            for (int jj = 0; jj < 8; ++jj) s[r] += hv[r][jj];
        #pragma unroll
        for (int o = 16; o; o >>= 1) {
            #pragma unroll
            for (int r = 0; r < 4; ++r) s[r] += __shfl_xor_sync(0xffffffffu, s[r], o);
        }
        float v[4] = {0.f, 0.f, 0.f, 0.f};
        float mean[4];
        #pragma unroll
        for (int r = 0; r < 4; ++r) {
            mean[r] = s[r] * (1.f/256.f);
            #pragma unroll
            for (int jj = 0; jj < 8; ++jj) { float t = hv[r][jj] - mean[r]; v[r] = fmaf(t, t, v[r]); }
        }
        #pragma unroll
        for (int o = 16; o; o >>= 1) {
            #pragma unroll
            for (int r = 0; r < 4; ++r) v[r] += __shfl_xor_sync(0xffffffffu, v[r], o);
        }
        #pragma unroll
        for (int r = 0; r < 4; ++r) {
            const float inv = rsqrtf(v[r] * (1.f/256.f) + 1e-5f);
            const bool valid = (rowBase + rl0 + r < N);
            #pragma unroll
            for (int jj = 0; jj < 8; ++jj) {
                const int d = lane + 32 * jj;
                float t = (hv[r][jj] - mean[r]) * inv * __ldg(gamma + d) + __ldg(beta + d);
                t = fmaxf(t, 0.f);
                if (!valid) t = 0.f;
                hs[(rl0 + r) * LDH + d] = __float2half(t);
            }
        }
    }
    __syncthreads();

    // ---- phase 2: GEMM 64x256x256 (single fp16 B), warp tile 64x32 ----
    const int c0 = wid * 32;

    wmma::fragment<wmma::accumulator, 16,16,16, float> acc[4][2];
    #pragma unroll
    for (int mi = 0; mi < 4; ++mi)
        #pragma unroll
        for (int ni = 0; ni < 2; ++ni) wmma::fill_fragment(acc[mi][ni], 0.f);

    #pragma unroll 1
    for (int t = 0; t < NCHUNK; ++t) {
        if (t <= NCHUNK - 3)      { cp_wait<2>(); }
        else if (t == NCHUNK - 2) { cp_wait<1>(); }
        else                      { cp_wait<0>(); }
        __syncthreads();
        if (t + 3 < NCHUNK) { load_chunk(smb, (t + 3) & 3, (t + 3) * 16, tid); cp_commit(); }

        const __half* bh0 = (const __half*)(sm + B_F) + (t & 3) * 4224;
        const int kk = t * 16;

        wmma::fragment<wmma::matrix_a, 16,16,16, __half, wmma::row_major> a[4];
        #pragma unroll
        for (int mi = 0; mi < 4; ++mi)
            wmma::load_matrix_sync(a[mi], hs + (mi*16) * LDH + kk, LDH);

        #pragma unroll
        for (int ni = 0; ni < 2; ++ni) {
            wmma::fragment<wmma::matrix_b, 16,16,16, __half, wmma::row_major> b;
            wmma::load_matrix_sync(b, bh0 + c0 + ni*16, LDH);
            #pragma unroll
            for (int mi = 0; mi < 4; ++mi)
                wmma::mma_sync(acc[mi][ni], a[mi], b, acc[mi][ni]);
        }
    }
    __syncthreads();   // hs + B dead; fs takes over

    // ---- phase 3: acc -> fs ; features = fs + b2 + Q -> out + fs (float4) ----
    #pragma unroll
    for (int mi = 0; mi < 4; ++mi)
        #pragma unroll
        for (int ni = 0; ni < 2; ++ni)
            wmma::store_matrix_sync(fs + (mi*16) * LDFS + c0 + ni*16,
                                    acc[mi][ni], LDFS, wmma::mem_row_major);
    __syncthreads();

    {
        const int rq = tid >> 6;             // 0..3
        const int c4 = (tid & 63) * 4;       // col group base
        #pragma unroll 1
        for (int g = 0; g < 4; ++g) {
            float4 qv[4];
            #pragma unroll
            for (int k = 0; k < 4; ++k) {
                const int rloc = g * 16 + k * 4 + rq;
                const int row = rowBase + rloc;
                qv[k] = (row < N) ? *(const float4*)&Q[(size_t)row * 256 + c4]
                                  : make_float4(0.f, 0.f, 0.f, 0.f);
            }
            #pragma unroll
            for (int k = 0; k < 4; ++k) {
                const int rloc = g * 16 + k * 4 + rq;
                const int row = rowBase + rloc;
                float4 fv = *(const float4*)&fs[rloc * LDFS + c4];
                fv.x = fv.x + b2v4.x + qv[k].x;
                fv.y = fv.y + b2v4.y + qv[k].y;
                fv.z = fv.z + b2v4.z + qv[k].z;
                fv.w = fv.w + b2v4.w + qv[k].w;
                if (row < N) *(float4*)&out[(size_t)row * 256 + c4] = fv;
                *(float4*)&fs[rloc * LDFS + c4] = fv;
            }
        }
    }
    __syncthreads();

    // ---- phase 3.5: lf logits = fs @ lfwt via tf32 wmma, split-K=2, no cvts ----
    {
        const int wm = wid & 3;       // 16-row frag
        const int nf = wid >> 2;      // 16-col frag (0/1)
        wmma::fragment<wmma::accumulator, 16,16,8, float> lacc0, lacc1;
        wmma::fill_fragment(lacc0, 0.f);
        wmma::fill_fragment(lacc1, 0.f);
        #pragma unroll 1
        for (int k = 0; k < 256; k += 16) {
            wmma::fragment<wmma::matrix_a, 16,16,8, wmma::precision::tf32, wmma::row_major> la0, la1;
            wmma::fragment<wmma::matrix_b, 16,16,8, wmma::precision::tf32, wmma::row_major> lb0, lb1;
            wmma::load_matrix_sync(la0, fs + (wm*16) * LDFS + k, LDFS);
            wmma::load_matrix_sync(lb0, lfwt + k * LDLW + nf*16, LDLW);
            wmma::load_matrix_sync(la1, fs + (wm*16) * LDFS + k + 8, LDFS);
            wmma::load_matrix_sync(lb1, lfwt + (k + 8) * LDLW + nf*16, LDLW);
            wmma::mma_sync(lacc0, la0, lb0, lacc0);
            wmma::mma_sync(lacc1, la1, lb1, lacc1);
        }
        #pragma unroll
        for (int e = 0; e < lacc0.num_elements; ++e) lacc0.x[e] += lacc1.x[e];
        wmma::store_matrix_sync(lfo + (wm*16) * LDLO + nf*16, lacc0, LDLO, wmma::mem_row_major);
    }
    __syncthreads();

    // ---- phase 4: sigmoid + corners + refs ----
    {
        const int rl    = wid * 8 + (lane >> 2);
        const int cpart = lane & 3;
        const int row   = rowBase + rl;

        if (row < N) {
            const float mx = mus[rl*3], my = mus[rl*3+1], mz = mus[rl*3+2];
            const float sx = scs[rl*3]*0.5f, sy = scs[rl*3+1]*0.5f, sz = scs[rl*3+2]*0.5f;
            float qw = rots[rl*4], qx = rots[rl*4+1], qy = rots[rl*4+2], qz = rots[rl*4+3];
            const float nrm = fmaxf(sqrtf(qw*qw + qx*qx + qy*qy + qz*qz), 1e-8f);
            const float inr = 1.f / nrm;
            qw *= inr; qx *= inr; qy *= inr; qz *= inr;
            const float r00 = 1.f - 2.f*(qy*qy + qz*qz), r01 = 2.f*(qx*qy - qz*qw), r02 = 2.f*(qx*qz + qy*qw);
            const float r10 = 2.f*(qx*qy + qz*qw), r11 = 1.f - 2.f*(qx*qx + qz*qz), r12 = 2.f*(qy*qz - qx*qw);
            const float r20 = 2.f*(qx*qz - qy*qw), r21 = 2.f*(qy*qz + qx*qw), r22 = 1.f - 2.f*(qx*qx + qy*qy);

            const size_t OUT_CORN = (size_t)N * 256;
            const size_t OUT_XY   = OUT_CORN + (size_t)N * 33;
            const size_t OUT_XZ   = OUT_XY + (size_t)N * 22;
            const size_t OUT_YZ   = OUT_XZ + (size_t)N * 22;
            const float invxy = 1.f / (102.4f + 1e-6f);
            const float invz  = 1.f / (8.0f + 1e-6f);

            #pragma unroll
            for (int mm = 0; mm < 3; ++mm) {
                const int m = cpart + mm * 4;
                if (m < 11) {
                    float lx, ly, lz;
                    if (m == 0)      { lx = 0.f;  ly = 0.f;  lz = 0.f; }
                    else if (m == 1) { lx = 0.f;  ly = sy;   lz = 0.f; }
                    else if (m == 2) { lx = 0.f;  ly = -sy;  lz = 0.f; }
                    else if (m == 3) { lx = sx;   ly = 0.f;  lz = 0.f; }
                    else if (m == 4) { lx = -sx;  ly = 0.f;  lz = 0.f; }
                    else {
                        const int j = (m - 5) * 3;
                        const float t0 = lfo[rl * LDLO + j]     + lfbs[j];
                        const float t1 = lfo[rl * LDLO + j + 1] + lfbs[j + 1];
                        const float t2 = lfo[rl * LDLO + j + 2] + lfbs[j + 2];
                        const float g0 = 1.f / (1.f + __expf(-t0));
                        const float g1 = 1.f / (1.f + __expf(-t1));
                        const float g2 = 1.f / (1.f + __expf(-t2));
                        lx = (g0 - 0.5f) * sx;
                        ly = (g1 - 0.5f) * sy;
                        lz = (g2 - 0.5f) * sz;
                    }
                    const float cxv = r00*lx + r01*ly + r02*lz + mx;
                    const float cyv = r10*lx + r11*ly + r12*lz + my;
                    const float czv = r20*lx + r21*ly + r22*lz + mz;
                    const size_t cb = OUT_CORN + ((size_t)row * 11 + m) * 3;
                    out[cb]   = cxv;
                    out[cb+1] = cyv;
                    out[cb+2] = czv;
                    const float nx = fminf(fmaxf((cxv + 51.2f) * invxy, 0.f), 1.f);
                    const float ny = fminf(fmaxf((cyv + 51.2f) * invxy, 0.f), 1.f);
                    const float nz = fminf(fmaxf((czv + 5.0f)  * invz,  0.f), 1.f);
                    const size_t rb2 = (size_t)row * 11 + m;
                    *(float2*)&out[OUT_XY + rb2*2] = make_float2(nx, ny);
                    *(float2*)&out[OUT_XZ + rb2*2] = make_float2(nx, nz);
                    *(float2*)&out[OUT_YZ + rb2*2] = make_float2(ny, nz);
                }
            }
        }
    }
}

extern "C" void kernel_launch(void* const* d_in, const int* in_sizes, int n_in,
                              void* d_out, int out_size) {
    const float* mu    = (const float*)d_in[0];
    const float* sc    = (const float*)d_in[1];
    const float* rot   = (const float*)d_in[2];
    const float* Q     = (const float*)d_in[3];
    const float* w1    = (const float*)d_in[4];
    const float* b1    = (const float*)d_in[5];
    const float* gamma = (const float*)d_in[6];
    const float* beta  = (const float*)d_in[7];
    const float* w2    = (const float*)d_in[8];
    const float* b2    = (const float*)d_in[9];
    const float* lfw   = (const float*)d_in[10];
    const float* lfb   = (const float*)d_in[11];
    float* out = (float*)d_out;
    const int N = in_sizes[0] / 3;

    w2_convert_kernel<<<256, 256>>>(w2, lfw);

    const int smem = SMEM_FLOATS * sizeof(float);
    cudaFuncSetAttribute(gauss_fused_kernel,
                         cudaFuncAttributeMaxDynamicSharedMemorySize, smem);
    const int blocks = (N + MT - 1) / MT;
    gauss_fused_kernel<<<blocks, 256, smem>>>(
        mu, sc, rot, Q, w1, b1, gamma, beta, b2, lfb, out, N);
}

// round 15
// speedup vs baseline: 1.1144x; 1.0813x over previous
#include <cuda_runtime.h>
#include <cuda_fp16.h>
#include <mma.h>
#include <cstdint>

using namespace nvcuda;
typedef unsigned int u32;

#define MT 64
#define LDH 264            // hs fp16 stride (528B rows)
#define LDFS 260           // fs fp32 stride
#define LDLW 36            // lfwt fp32 stride
#define LDLO 32            // lfout fp32 stride
#define NCHUNK 16

// ---------------- smem layout (floats) ----------------
#define HS_F    0
#define B_F     8448
#define GEO_F   16896
#define LFWT_F  17536
#define LFO_F   26752
#define LFB_F   28800
#define SMEM_FLOATS 28832            // 115,328 B -> 2 CTAs/SM

__device__ __half g_w2h[256 * 256];    // [K][N] fp16
__device__ float  g_lfwt[256 * LDLW];  // [K=256][36] padded lfw, tf32-pre-rounded

__device__ __forceinline__ u32 smem_u32(const void* p) {
    return (u32)__cvta_generic_to_shared(p);
}
__device__ __forceinline__ void cp_async16(u32 s, const void* g) {
    asm volatile("cp.async.cg.shared.global [%0], [%1], 16;" :: "r"(s), "l"(g));
}
__device__ __forceinline__ void cp_commit() { asm volatile("cp.async.commit_group;"); }
template<int NN> __device__ __forceinline__ void cp_wait() {
    asm volatile("cp.async.wait_group %0;" :: "n"(NN) : "memory");
}
__device__ __forceinline__ float to_tf32(float x) {
    float r;
    asm("cvt.rna.tf32.f32 %0, %1;" : "=f"(r) : "f"(x));
    return r;
}

__global__ void w2_convert_kernel(const float* __restrict__ w2,
                                  const float* __restrict__ lfw) {
    const int k = blockIdx.x, n = threadIdx.x;
    g_w2h[k * 256 + n] = __float2half(w2[k * 256 + n]);
    if (n < LDLW)
        g_lfwt[k * LDLW + n] = (n < 18) ? to_tf32(lfw[k * 18 + n]) : 0.f;
}

// stage a 16-k-row chunk of w2 fp16 into buffer buf (0..3)
__device__ __forceinline__ void load_chunk(u32 smb, int buf, int kt, int tid) {
    const u32 base = smb + B_F * 4 + buf * 8448;
    #pragma unroll
    for (int q = 0; q < 2; ++q) {
        const int idx = tid + 256 * q;          // 0..511
        const int r   = idx >> 5;               // k-row 0..15
        const int j   = idx & 31;               // 8-fp16 chunk
        cp_async16(base + r * 528 + j * 16, g_w2h + (kt + r) * 256 + j * 8);
    }
}

// =================== Fused kernel ===================
__global__ void __launch_bounds__(256, 2)
gauss_fused_kernel(const float* __restrict__ mu, const float* __restrict__ sc,
                   const float* __restrict__ rot, const float* __restrict__ Q,
                   const float* __restrict__ w1, const float* __restrict__ b1,
                   const float* __restrict__ gamma, const float* __restrict__ beta,
                   const float* __restrict__ b2, const float* __restrict__ lfb,
                   float* __restrict__ out, int N)
{
    extern __shared__ float sm[];
    const u32 smb = smem_u32(sm);
    __half* hs  = (__half*)(sm + HS_F);
    float* fs   = sm + HS_F;            // overlays hs+B post-GEMM
    float* mus  = sm + GEO_F;           // 192
    float* scs  = sm + GEO_F + 192;     // 192
    float* rots = sm + GEO_F + 384;     // 256
    float* lfwt = sm + LFWT_F;
    float* lfo  = sm + LFO_F;
    float* lfbs = sm + LFB_F;

    const int tid  = threadIdx.x;
    const int lane = tid & 31;
    const int wid  = tid >> 5;
    const int rowBase = blockIdx.x * MT;
    const bool fullTile = (rowBase + MT <= N);

    // ---- group G: lfwt + geo ----
    {
        const u32 lfdst = smb + LFWT_F * 4;
        #pragma unroll
        for (int q = 0; q < 9; ++q) {
            const int c = tid + 256 * q;      // 0..2303 chunks of 16B
            cp_async16(lfdst + c * 16, g_lfwt + c * 4);
        }
        if (fullTile) {
            if (tid < 48)
                cp_async16(smb + (GEO_F + tid * 4) * 4, mu + (size_t)rowBase * 3 + tid * 4);
            else if (tid >= 64 && tid < 112)
                cp_async16(smb + (GEO_F + 192 + (tid - 64) * 4) * 4, sc + (size_t)rowBase * 3 + (tid - 64) * 4);
            else if (tid >= 128 && tid < 192)
                cp_async16(smb + (GEO_F + 384 + (tid - 128) * 4) * 4, rot + (size_t)rowBase * 4 + (tid - 128) * 4);
        } else {
            #pragma unroll 1
            for (int idx = tid; idx < 640; idx += 256) {
                float v = 0.f;
                if (idx < 192)      { const int r = idx / 3;         if (rowBase + r < N) v = mu[(size_t)(rowBase + r) * 3 + idx % 3]; }
                else if (idx < 384) { const int r = (idx - 192) / 3; if (rowBase + r < N) v = sc[(size_t)(rowBase + r) * 3 + (idx - 192) % 3]; }
                else                { const int r = (idx - 384) / 4; if (rowBase + r < N) v = rot[(size_t)(rowBase + r) * 4 + (idx - 384) % 4]; }
                sm[GEO_F + idx] = v;
            }
        }
    }
    cp_commit();                                     // [G]
    load_chunk(smb, 0, 0, tid);  cp_commit();        // [G][B0]
    load_chunk(smb, 1, 16, tid); cp_commit();        // [G][B0][B1]
    load_chunk(smb, 2, 32, tid); cp_commit();        // [G][B0][B1][B2]

    if (tid < 18) lfbs[tid] = lfb[tid];
    const float4 b2v4 = __ldg((const float4*)(b2 + (tid & 63) * 4));

    cp_wait<3>();          // G done; B0..B2 in flight
    __syncthreads();

    // ---- phase 1: h = relu(LN(geo@w1+b1)) -> hs fp16 ----
    // vectorized: thread handles 8 consecutive cols d0..d0+7, float4 loads, STS.128 store
    const int d0 = lane * 8;
    #pragma unroll 1
    for (int bb = 0; bb < 2; ++bb) {
        const int rl0 = wid * 8 + bb * 4;
        float g[4][10];
        #pragma unroll
        for (int r = 0; r < 4; ++r) {
            const int rl = rl0 + r;
            g[r][0]=mus[rl*3]; g[r][1]=mus[rl*3+1]; g[r][2]=mus[rl*3+2];
            g[r][3]=scs[rl*3]; g[r][4]=scs[rl*3+1]; g[r][5]=scs[rl*3+2];
            g[r][6]=rots[rl*4]; g[r][7]=rots[rl*4+1]; g[r][8]=rots[rl*4+2]; g[r][9]=rots[rl*4+3];
        }
        float hv[4][8];
        {
            const float4 ba = __ldg((const float4*)(b1 + d0));
            const float4 bbv = __ldg((const float4*)(b1 + d0 + 4));
            #pragma unroll
            for (int r = 0; r < 4; ++r) {
                hv[r][0]=ba.x; hv[r][1]=ba.y; hv[r][2]=ba.z; hv[r][3]=ba.w;
                hv[r][4]=bbv.x; hv[r][5]=bbv.y; hv[r][6]=bbv.z; hv[r][7]=bbv.w;
            }
        }
        #pragma unroll
        for (int i = 0; i < 10; ++i) {
            const float4 wa = __ldg((const float4*)(w1 + i * 256 + d0));
            const float4 wb = __ldg((const float4*)(w1 + i * 256 + d0 + 4));
            const float w[8] = {wa.x, wa.y, wa.z, wa.w, wb.x, wb.y, wb.z, wb.w};
            #pragma unroll
            for (int r = 0; r < 4; ++r)
                #pragma unroll
                for (int jj = 0; jj < 8; ++jj)
                    hv[r][jj] = fmaf(g[r][i], w[jj], hv[r][jj]);
        }
        float s[4] = {0.f, 0.f, 0.f, 0.f};
        #pragma unroll
        for (int r = 0; r < 4; ++r)
            #pragma unroll
            for (int jj = 0; jj < 8; ++jj) s[r] += hv[r][jj];
        #pragma unroll
        for (int o = 16; o; o >>= 1) {
            #pragma unroll
            for (int r = 0; r < 4; ++r) s[r] += __shfl_xor_sync(0xffffffffu, s[r], o);
        }
        float v[4] = {0.f, 0.f, 0.f, 0.f};
        float mean[4];
        #pragma unroll
        for (int r = 0; r < 4; ++r) {
            mean[r] = s[r] * (1.f/256.f);
            #pragma unroll
            for (int jj = 0; jj < 8; ++jj) { float t = hv[r][jj] - mean[r]; v[r] = fmaf(t, t, v[r]); }
        }
        #pragma unroll
        for (int o = 16; o; o >>= 1) {
            #pragma unroll
            for (int r = 0; r < 4; ++r) v[r] += __shfl_xor_sync(0xffffffffu, v[r], o);
        }
        const float4 gma = __ldg((const float4*)(gamma + d0));
        const float4 gmb = __ldg((const float4*)(gamma + d0 + 4));
        const float4 bta = __ldg((const float4*)(beta + d0));
        const float4 btb = __ldg((const float4*)(beta + d0 + 4));
        const float gm[8] = {gma.x, gma.y, gma.z, gma.w, gmb.x, gmb.y, gmb.z, gmb.w};
        const float bt[8] = {bta.x, bta.y, bta.z, bta.w, btb.x, btb.y, btb.z, btb.w};
        #pragma unroll
        for (int r = 0; r < 4; ++r) {
            const float inv = rsqrtf(v[r] * (1.f/256.f) + 1e-5f);
            const bool valid = (rowBase + rl0 + r < N);
            __half2 h01, h23, h45, h67;
            {
                float t[8];
                #pragma unroll
                for (int jj = 0; jj < 8; ++jj) {
                    float x = (hv[r][jj] - mean[r]) * inv * gm[jj] + bt[jj];
                    x = fmaxf(x, 0.f);
                    if (!valid) x = 0.f;
                    t[jj] = x;
                }
                h01 = __floats2half2_rn(t[0], t[1]);
                h23 = __floats2half2_rn(t[2], t[3]);
                h45 = __floats2half2_rn(t[4], t[5]);
                h67 = __floats2half2_rn(t[6], t[7]);
            }
            uint4 pk;
            pk.x = *(u32*)&h01; pk.y = *(u32*)&h23;
            pk.z = *(u32*)&h45; pk.w = *(u32*)&h67;
            *(uint4*)&hs[(rl0 + r) * LDH + d0] = pk;
        }
    }
    __syncthreads();

    // ---- phase 2: GEMM 64x256x256 (single fp16 B), warp tile 64x32 ----
    const int c0 = wid * 32;

    wmma::fragment<wmma::accumulator, 16,16,16, float> acc[4][2];
    #pragma unroll
    for (int mi = 0; mi < 4; ++mi)
        #pragma unroll
        for (int ni = 0; ni < 2; ++ni) wmma::fill_fragment(acc[mi][ni], 0.f);

    #pragma unroll 1
    for (int t = 0; t < NCHUNK; ++t) {
        if (t <= NCHUNK - 3)      { cp_wait<2>(); }
        else if (t == NCHUNK - 2) { cp_wait<1>(); }
        else                      { cp_wait<0>(); }
        __syncthreads();
        if (t + 3 < NCHUNK) { load_chunk(smb, (t + 3) & 3, (t + 3) * 16, tid); cp_commit(); }

        const __half* bh0 = (const __half*)(sm + B_F) + (t & 3) * 4224;
        const int kk = t * 16;

        wmma::fragment<wmma::matrix_a, 16,16,16, __half, wmma::row_major> a[4];
        #pragma unroll
        for (int mi = 0; mi < 4; ++mi)
            wmma::load_matrix_sync(a[mi], hs + (mi*16) * LDH + kk, LDH);

        #pragma unroll
        for (int ni = 0; ni < 2; ++ni) {
            wmma::fragment<wmma::matrix_b, 16,16,16, __half, wmma::row_major> b;
            wmma::load_matrix_sync(b, bh0 + c0 + ni*16, LDH);
            #pragma unroll
            for (int mi = 0; mi < 4; ++mi)
                wmma::mma_sync(acc[mi][ni], a[mi], b, acc[mi][ni]);
        }
    }
    __syncthreads();   // hs + B dead; fs takes over

    // ---- phase 3: acc -> fs ; features = fs + b2 + Q -> out + fs (float4) ----
    #pragma unroll
    for (int mi = 0; mi < 4; ++mi)
        #pragma unroll
        for (int ni = 0; ni < 2; ++ni)
            wmma::store_matrix_sync(fs + (mi*16) * LDFS + c0 + ni*16,
                                    acc[mi][ni], LDFS, wmma::mem_row_major);
    __syncthreads();

    {
        const int rq = tid >> 6;             // 0..3
        const int c4 = (tid & 63) * 4;       // col group base
        #pragma unroll 1
        for (int g = 0; g < 4; ++g) {
            float4 qv[4];
            #pragma unroll
            for (int k = 0; k < 4; ++k) {
                const int rloc = g * 16 + k * 4 + rq;
                const int row = rowBase + rloc;
                qv[k] = (row < N) ? *(const float4*)&Q[(size_t)row * 256 + c4]
                                  : make_float4(0.f, 0.f, 0.f, 0.f);
            }
            #pragma unroll
            for (int k = 0; k < 4; ++k) {
                const int rloc = g * 16 + k * 4 + rq;
                const int row = rowBase + rloc;
                float4 fv = *(const float4*)&fs[rloc * LDFS + c4];
                fv.x = fv.x + b2v4.x + qv[k].x;
                fv.y = fv.y + b2v4.y + qv[k].y;
                fv.z = fv.z + b2v4.z + qv[k].z;
                fv.w = fv.w + b2v4.w + qv[k].w;
                if (row < N) *(float4*)&out[(size_t)row * 256 + c4] = fv;
                *(float4*)&fs[rloc * LDFS + c4] = fv;
            }
        }
    }
    __syncthreads();

    // ---- phase 3.5: lf logits = fs @ lfwt via tf32 wmma, split-K=2, no cvts ----
    {
        const int wm = wid & 3;       // 16-row frag
        const int nf = wid >> 2;      // 16-col frag (0/1)
        wmma::fragment<wmma::accumulator, 16,16,8, float> lacc0, lacc1;
        wmma::fill_fragment(lacc0, 0.f);
        wmma::fill_fragment(lacc1, 0.f);
        #pragma unroll 1
        for (int k = 0; k < 256; k += 16) {
            wmma::fragment<wmma::matrix_a, 16,16,8, wmma::precision::tf32, wmma::row_major> la0, la1;
            wmma::fragment<wmma::matrix_b, 16,16,8, wmma::precision::tf32, wmma::row_major> lb0, lb1;
            wmma::load_matrix_sync(la0, fs + (wm*16) * LDFS + k, LDFS);
            wmma::load_matrix_sync(lb0, lfwt + k * LDLW + nf*16, LDLW);
            wmma::load_matrix_sync(la1, fs + (wm*16) * LDFS + k + 8, LDFS);
            wmma::load_matrix_sync(lb1, lfwt + (k + 8) * LDLW + nf*16, LDLW);
            wmma::mma_sync(lacc0, la0, lb0, lacc0);
            wmma::mma_sync(lacc1, la1, lb1, lacc1);
        }
        #pragma unroll
        for (int e = 0; e < lacc0.num_elements; ++e) lacc0.x[e] += lacc1.x[e];
        wmma::store_matrix_sync(lfo + (wm*16) * LDLO + nf*16, lacc0, LDLO, wmma::mem_row_major);
    }
    __syncthreads();

    // ---- phase 4: sigmoid + corners + refs ----
    {
        const int rl    = wid * 8 + (lane >> 2);
        const int cpart = lane & 3;
        const int row   = rowBase + rl;

        if (row < N) {
            const float mx = mus[rl*3], my = mus[rl*3+1], mz = mus[rl*3+2];
            const float sx = scs[rl*3]*0.5f, sy = scs[rl*3+1]*0.5f, sz = scs[rl*3+2]*0.5f;
            float qw = rots[rl*4], qx = rots[rl*4+1], qy = rots[rl*4+2], qz = rots[rl*4+3];
            const float nrm = fmaxf(sqrtf(qw*qw + qx*qx + qy*qy + qz*qz), 1e-8f);
            const float inr = 1.f / nrm;
            qw *= inr; qx *= inr; qy *= inr; qz *= inr;
            const float r00 = 1.f - 2.f*(qy*qy + qz*qz), r01 = 2.f*(qx*qy - qz*qw), r02 = 2.f*(qx*qz + qy*qw);
            const float r10 = 2.f*(qx*qy + qz*qw), r11 = 1.f - 2.f*(qx*qx + qz*qz), r12 = 2.f*(qy*qz - qx*qw);
            const float r20 = 2.f*(qx*qz - qy*qw), r21 = 2.f*(qy*qz + qx*qw), r22 = 1.f - 2.f*(qx*qx + qy*qy);

            const size_t OUT_CORN = (size_t)N * 256;
            const size_t OUT_XY   = OUT_CORN + (size_t)N * 33;
            const size_t OUT_XZ   = OUT_XY + (size_t)N * 22;
            const size_t OUT_YZ   = OUT_XZ + (size_t)N * 22;
            const float invxy = 1.f / (102.4f + 1e-6f);
            const float invz  = 1.f / (8.0f + 1e-6f);

            #pragma unroll
            for (int mm = 0; mm < 3; ++mm) {
                const int m = cpart + mm * 4;
                if (m < 11) {
                    float lx, ly, lz;
                    if (m == 0)      { lx = 0.f;  ly = 0.f;  lz = 0.f; }
                    else if (m == 1) { lx = 0.f;  ly = sy;   lz = 0.f; }
                    else if (m == 2) { lx = 0.f;  ly = -sy;  lz = 0.f; }
                    else if (m == 3) { lx = sx;   ly = 0.f;  lz = 0.f; }
                    else if (m == 4) { lx = -sx;  ly = 0.f;  lz = 0.f; }
                    else {
                        const int j = (m - 5) * 3;
                        const float t0 = lfo[rl * LDLO + j]     + lfbs[j];
                        const float t1 = lfo[rl * LDLO + j + 1] + lfbs[j + 1];
                        const float t2 = lfo[rl * LDLO + j + 2] + lfbs[j + 2];
                        const float g0 = 1.f / (1.f + __expf(-t0));
                        const float g1 = 1.f / (1.f + __expf(-t1));
                        const float g2 = 1.f / (1.f + __expf(-t2));
                        lx = (g0 - 0.5f) * sx;
                        ly = (g1 - 0.5f) * sy;
                        lz = (g2 - 0.5f) * sz;
                    }
                    const float cxv = r00*lx + r01*ly + r02*lz + mx;
                    const float cyv = r10*lx + r11*ly + r12*lz + my;
                    const float czv = r20*lx + r21*ly + r22*lz + mz;
                    const size_t cb = OUT_CORN + ((size_t)row * 11 + m) * 3;
                    out[cb]   = cxv;
                    out[cb+1] = cyv;
                    out[cb+2] = czv;
                    const float nx = fminf(fmaxf((cxv + 51.2f) * invxy, 0.f), 1.f);
                    const float ny = fminf(fmaxf((cyv + 51.2f) * invxy, 0.f), 1.f);
                    const float nz = fminf(fmaxf((czv + 5.0f)  * invz,  0.f), 1.f);
                    const size_t rb2 = (size_t)row * 11 + m;
                    *(float2*)&out[OUT_XY + rb2*2] = make_float2(nx, ny);
                    *(float2*)&out[OUT_XZ + rb2*2] = make_float2(nx, nz);
                    *(float2*)&out[OUT_YZ + rb2*2] = make_float2(ny, nz);
                }
            }
        }
    }
}

extern "C" void kernel_launch(void* const* d_in, const int* in_sizes, int n_in,
                              void* d_out, int out_size) {
    const float* mu    = (const float*)d_in[0];
    const float* sc    = (const float*)d_in[1];
    const float* rot   = (const float*)d_in[2];
    const float* Q     = (const float*)d_in[3];
    const float* w1    = (const float*)d_in[4];
    const float* b1    = (const float*)d_in[5];
    const float* gamma = (const float*)d_in[6];
    const float* beta  = (const float*)d_in[7];
    const float* w2    = (const float*)d_in[8];
    const float* b2    = (const float*)d_in[9];
    const float* lfw   = (const float*)d_in[10];
    const float* lfb   = (const float*)d_in[11];
    float* out = (float*)d_out;
    const int N = in_sizes[0] / 3;

    w2_convert_kernel<<<256, 256>>>(w2, lfw);

    const int smem = SMEM_FLOATS * sizeof(float);
    cudaFuncSetAttribute(gauss_fused_kernel,
                         cudaFuncAttributeMaxDynamicSharedMemorySize, smem);
    const int blocks = (N + MT - 1) / MT;
    gauss_fused_kernel<<<blocks, 256, smem>>>(
        mu, sc, rot, Q, w1, b1, gamma, beta, b2, lfb, out, N);
}